// round 14
// baseline (speedup 1.0000x reference)
#include <cuda_runtime.h>
#include <cuda_bf16.h>
#include <math.h>

#define T_STEPS 100
#define BATCH   64
#define HID     512
#define NGATE   2048   // 4*512
#define VOCAB   10000
#define NVPAD   10240  // vocab padded to 256
#define NBLK    128
#define BH      (BATCH * HID)

typedef unsigned long long u64;

// ------------------------- scratch (static device memory) -------------------
__device__ float g_XW1[T_STEPS * 4 * HID * BATCH];    // [t][g][o][b] k-major
__device__ float g_AfragH2[T_STEPS * BATCH * HID];    // h2 in A-fragment order
__device__ float g_BfragDec[NVPAD * HID];             // dec_w in B-fragment order
__device__ float g_h1buf[2 * BH];                     // K-MAJOR: [k][64 b]
__device__ float g_h2buf[2 * BH];                     // K-MAJOR: [k][64 b]
__device__ float g_c1f[BH];
__device__ float g_c2f[BH];
__device__ unsigned g_bar_cnt;
__device__ volatile unsigned g_bar_flag;

// ------------------------- f32x2 helpers -------------------------------------
__device__ __forceinline__ u64 pack2(float x, float y) {
    u64 r;
    asm("mov.b64 %0, {%1, %2};" : "=l"(r)
        : "r"(__float_as_uint(x)), "r"(__float_as_uint(y)));
    return r;
}
__device__ __forceinline__ u64 dup2(float x) {
    u64 r;
    asm("mov.b64 %0, {%1, %1};" : "=l"(r) : "r"(__float_as_uint(x)));
    return r;
}
__device__ __forceinline__ void fma2(u64 &d, u64 a, u64 b) {
    asm("fma.rn.f32x2 %0, %1, %2, %0;" : "+l"(d) : "l"(a), "l"(b));
}
__device__ __forceinline__ void add2(u64 &d, u64 a) {
    asm("add.rn.f32x2 %0, %0, %1;" : "+l"(d) : "l"(a));
}
__device__ __forceinline__ float2 unpack2(u64 v) {
    float2 r;
    r.x = __uint_as_float((unsigned)(v & 0xFFFFFFFFu));
    r.y = __uint_as_float((unsigned)(v >> 32));
    return r;
}
__device__ __forceinline__ float sigm(float x) { return 1.f / (1.f + expf(-x)); }

// ------------------------- tf32 mma helpers ----------------------------------
__device__ __forceinline__ float cvt_tf32(float x) {
    unsigned r;
    asm("cvt.rn.tf32.f32 %0, %1;" : "=r"(r) : "f"(x));
    return __uint_as_float(r);
}
__device__ __forceinline__ void mma_tf32(float* d, const uint4& a, const uint2& b) {
    asm("mma.sync.aligned.m16n8k8.row.col.f32.tf32.tf32.f32 "
        "{%0,%1,%2,%3}, {%4,%5,%6,%7}, {%8,%9}, {%0,%1,%2,%3};"
        : "+f"(d[0]), "+f"(d[1]), "+f"(d[2]), "+f"(d[3])
        : "r"(a.x), "r"(a.y), "r"(a.z), "r"(a.w), "r"(b.x), "r"(b.y));
}

// ------------------------- cp.async helpers ----------------------------------
__device__ __forceinline__ void cp_async16(void* dst, const void* src) {
    unsigned d = (unsigned)__cvta_generic_to_shared(dst);
    asm volatile("cp.async.cg.shared.global [%0], [%1], 16;" :: "r"(d), "l"(src));
}
__device__ __forceinline__ void cp_commit() {
    asm volatile("cp.async.commit_group;");
}
template<int N> __device__ __forceinline__ void cp_wait() {
    asm volatile("cp.async.wait_group %0;" :: "n"(N));
}

// ------------------------- init (transpose states to k-major) ----------------
__global__ void init_state(const float* __restrict__ h1, const float* __restrict__ h2) {
    int i = blockIdx.x * blockDim.x + threadIdx.x;
    if (i < BH) {
        int k = i >> 6, b = i & 63;
        g_h1buf[i] = h1[b * HID + k];       // slot 0 = h1(-1)
        g_h2buf[BH + i] = h2[b * HID + k];
        g_h2buf[i] = h2[b * HID + k];       // slot 0 = h2(-1) (phase 1 reads slot 0)
    }
    if (i == 0) { g_bar_cnt = 0; g_bar_flag = 0; }
}

// ------------------------- conv: dec_w -> B-fragment order -------------------
__global__ __launch_bounds__(256) void conv_b_dec(const float* __restrict__ Bw) {
    const int n  = blockIdx.x * 256 + threadIdx.x;   // 0..10239
    const int kg = blockIdx.y;                       // 0..63
    const int k0 = kg * 8;

    float v[8];
    if (n < VOCAB) {
        float4 a = *(const float4*)(Bw + (size_t)n * HID + k0);
        float4 b = *(const float4*)(Bw + (size_t)n * HID + k0 + 4);
        v[0]=a.x; v[1]=a.y; v[2]=a.z; v[3]=a.w;
        v[4]=b.x; v[5]=b.y; v[6]=b.z; v[7]=b.w;
    } else {
#pragma unroll
        for (int j = 0; j < 8; j++) v[j] = 0.f;
    }
    const int nb = n >> 8, nn = n & 255, natom = nn >> 3, g = nn & 7;
    const int kc = k0 >> 5, ka = (k0 & 31) >> 3;
    float* dst = g_BfragDec +
        ((((size_t)(nb * 16 + kc) * 32 + natom) * 4 + ka) * 32 + g * 4) * 2;
    float4 o0 = make_float4(cvt_tf32(v[0]), cvt_tf32(v[4]), cvt_tf32(v[1]), cvt_tf32(v[5]));
    float4 o1 = make_float4(cvt_tf32(v[2]), cvt_tf32(v[6]), cvt_tf32(v[3]), cvt_tf32(v[7]));
    *(float4*)dst       = o0;
    *(float4*)(dst + 4) = o1;
}

// ------------------------- precompute XW1 = emb[tok] @ wi1 -------------------
// Output layout: g_XW1[t][g][o][b].  Double-buffered: A prefetched to regs,
// B staged via cp.async; ONE __syncthreads per 8-k chunk.
__global__ __launch_bounds__(256) void precompute_xw1(
    const int* __restrict__ tok, const float* __restrict__ emb,
    const float* __restrict__ wi1)
{
    __shared__ float As[2][8][128];
    __shared__ float Bs[2][8][128];
    __shared__ int   toks[128];

    const int tid = threadIdx.x;
    const int m0 = blockIdx.y * 128;
    const int n0 = blockIdx.x * 128;
    const int g  = n0 >> 9;
    const int og0 = n0 & 511;
    const float* wbase = wi1 + (size_t)g * HID * HID + og0;

    if (tid < 128) toks[tid] = tok[m0 + tid];
    __syncthreads();

    const int lr = tid >> 1;
    const int lk = (tid & 1) * 4;
    const int bk = tid >> 5;
    const int bn = (tid & 31) * 4;
    const int tx = tid & 15, ty = tid >> 4;

    const float* a_src = emb + (size_t)toks[lr] * HID + lk;
    const float* b_src = wbase + (size_t)bk * HID + bn;

    u64 acc[8][4];
#pragma unroll
    for (int i = 0; i < 8; i++)
#pragma unroll
        for (int j = 0; j < 4; j++) acc[i][j] = 0ULL;

    // prologue: stage chunk 0
    {
        float4 av = *(const float4*)(a_src);
        cp_async16(&Bs[0][bk][bn], b_src);
        cp_commit();
        As[0][lk+0][lr] = av.x; As[0][lk+1][lr] = av.y;
        As[0][lk+2][lr] = av.z; As[0][lk+3][lr] = av.w;
        cp_wait<0>();
        __syncthreads();
    }

    for (int c = 0; c < 64; c++) {
        const int cur = c & 1, nxt = cur ^ 1;
        float4 avn;
        if (c < 63) {
            avn = *(const float4*)(a_src + (size_t)(c + 1) * 8);
            cp_async16(&Bs[nxt][bk][bn], b_src + (size_t)(c + 1) * 8 * HID);
            cp_commit();
        }
#pragma unroll
        for (int k = 0; k < 8; k++) {
            float4 a0 = *(float4*)&As[cur][k][ty * 4];
            float4 a1 = *(float4*)&As[cur][k][64 + ty * 4];
            float4 b0 = *(float4*)&Bs[cur][k][tx * 4];
            float4 b1 = *(float4*)&Bs[cur][k][64 + tx * 4];
            u64 bp0 = ((const u64*)&b0)[0], bp1 = ((const u64*)&b0)[1];
            u64 bp2 = ((const u64*)&b1)[0], bp3 = ((const u64*)&b1)[1];
            float ar[8] = {a0.x, a0.y, a0.z, a0.w, a1.x, a1.y, a1.z, a1.w};
#pragma unroll
            for (int i = 0; i < 8; i++) {
                u64 ad = dup2(ar[i]);
                fma2(acc[i][0], ad, bp0);
                fma2(acc[i][1], ad, bp1);
                fma2(acc[i][2], ad, bp2);
                fma2(acc[i][3], ad, bp3);
            }
        }
        if (c < 63) {
            As[nxt][lk+0][lr] = avn.x; As[nxt][lk+1][lr] = avn.y;
            As[nxt][lk+2][lr] = avn.z; As[nxt][lk+3][lr] = avn.w;
            cp_wait<0>();
        }
        __syncthreads();
    }

    // scatter epilogue: element (m, n=g*512+o) -> g_XW1[((t*4+g)*512+o)*64+b]
#pragma unroll
    for (int i = 0; i < 8; i++) {
        int m = m0 + (i < 4 ? ty * 4 + i : 64 + ty * 4 + (i - 4));
        int t = m >> 6, b = m & 63;
        float* tb = g_XW1 + (((size_t)t * 4 + g) * HID) * BATCH + b;
#pragma unroll
        for (int j = 0; j < 4; j++) {
            float2 v = unpack2(acc[i][j]);
            int cb = (j < 2) ? (tx * 4 + j * 2) : (64 + tx * 4 + (j - 2) * 2);
            int o = og0 + cb;
            tb[(size_t)o * BATCH]       = v.x;
            tb[(size_t)(o + 1) * BATCH] = v.y;
        }
    }
}

// ------------------------- persistent recurrence kernel ----------------------
// WAVEFRONT + 8-way reduce split (R13), with software-pipelined gemm_b4:
// group n+1's h loads are issued before group n's FMAs consume group n.
struct SmemT {
    float w1 [HID * 16];    // [k][oo][g]
    float wi2[HID * 16];
    float wh2[HID * 16];
    u64   xchA[8 * 64 * 8]; // layer1 partials [ks][r][8]
    u64   xchB[8 * 64 * 8]; // layer2 partials [ks][r][8]
    float c1s[256];         // [b][oo]
    float c2s[256];
};

__device__ __forceinline__ void grid_barrier(int p) {
    __syncthreads();
    if (threadIdx.x == 0) {
        __threadfence();   // release (emits CCTL.IVALL too)
        unsigned prev = atomicAdd(&g_bar_cnt, 1u);
        if (prev == (unsigned)NBLK * (unsigned)(p + 1) - 1u) {
            g_bar_flag = (unsigned)(p + 1);
        } else {
            while (g_bar_flag < (unsigned)(p + 1)) { }
        }
        __threadfence();   // acquire + invalidate this SM's L1D
    }
    __syncthreads();
}

// one 4k group of FMAs (identical per-k order to previous rounds)
__device__ __forceinline__ void fma_group(
    const float4 (&hv)[4], const float* __restrict__ w, int kk, u64 (&acc)[8])
{
#pragma unroll
    for (int j = 0; j < 4; j++) {
        float4 wv = *(const float4*)(w + (kk + j) * 16);
        u64 w0 = ((const u64*)&wv)[0];
        u64 w1 = ((const u64*)&wv)[1];
        u64 d0 = dup2(hv[j].x), d1 = dup2(hv[j].y);
        u64 d2 = dup2(hv[j].z), d3 = dup2(hv[j].w);
        fma2(acc[0], d0, w0); fma2(acc[1], d0, w1);
        fma2(acc[2], d1, w0); fma2(acc[3], d1, w1);
        fma2(acc[4], d2, w0); fma2(acc[5], d2, w1);
        fma2(acc[6], d3, w0); fma2(acc[7], d3, w1);
    }
}

// acc[b*2+0] = {i,f}, acc[b*2+1] = {g,o} for 4 batches b.
// Software-pipelined: two named 4k register groups, prefetch distance 1.
__device__ __forceinline__ void gemm_b4(
    const float* __restrict__ hk,     // k-major h + b0 offset
    const float* __restrict__ w,      // smem weights + oo*4
    int klen, u64 (&acc)[8])
{
    float4 ga[4], gb[4];
#pragma unroll
    for (int j = 0; j < 4; j++)
        ga[j] = *(const float4*)(hk + (size_t)j * BATCH);
#pragma unroll 1
    for (int kk = 0; kk < klen; kk += 8) {
        // prefetch group B (kk+4..kk+7) while computing group A (kk..kk+3)
#pragma unroll
        for (int j = 0; j < 4; j++)
            gb[j] = *(const float4*)(hk + (size_t)(kk + 4 + j) * BATCH);
        fma_group(ga, w, kk, acc);
        // prefetch next group A (kk+8..kk+11) while computing group B
        if (kk + 8 < klen) {
#pragma unroll
            for (int j = 0; j < 4; j++)
                ga[j] = *(const float4*)(hk + (size_t)(kk + 8 + j) * BATCH);
        }
        fma_group(gb, w, kk + 4, acc);
    }
}

// h2 value (m = t*64+b, k = col) -> A-fragment global index
__device__ __forceinline__ size_t afrag_idx(int m, int kc, int ka, int lk, int khi) {
    int mb = m >> 7, mm = m & 127, matom = mm >> 4, r16 = mm & 15;
    int lane = (r16 & 7) * 4 + lk;
    int reg  = (r16 >> 3) + 2 * khi;
    return ((((size_t)(mb * 16 + kc) * 8 + matom) * 4 + ka) * 32 + lane) * 4 + reg;
}

__global__ __launch_bounds__(512, 1) void lstm_recur(
    const float* __restrict__ wh1, const float* __restrict__ wi2g,
    const float* __restrict__ wh2g,
    const float* __restrict__ c1in, const float* __restrict__ c2in)
{
    extern __shared__ char smraw[];
    SmemT* sm = (SmemT*)smraw;
    const int tid = threadIdx.x;
    const int bi  = blockIdx.x;
    const int o0  = bi * 4;

    // weights: [k][oo][g] <- W[g][k][o0+oo], once for all phases
    for (int idx = tid; idx < HID * 16; idx += 512) {
        int k = idx >> 4, c = idx & 15;
        int oo = c >> 2, g = c & 3;
        size_t src = ((size_t)g * HID + k) * HID + o0 + oo;
        sm->w1 [idx] = wh1 [src];
        sm->wi2[idx] = wi2g[src];
        sm->wh2[idx] = wh2g[src];
    }
    if (tid < 256) {   // c state slice [b][oo]
        int b = tid >> 2, oo = tid & 3;
        sm->c1s[tid] = c1in[b * HID + o0 + oo];
        sm->c2s[tid] = c2in[b * HID + o0 + oo];
    }
    __syncthreads();

    const int ks = tid >> 6;        // 0..7
    const int r  = tid & 63;
    const int oo = r & 3;
    const int bq = r >> 2;
    const int b0 = bq * 4;
    const int col = o0 + oo;

    // A-fragment constants for (k = col)
    const int f_kc = col >> 5, f_kk = col & 31;
    const int f_ka = f_kk >> 3, f_lk = f_kk & 3, f_khi = (f_kk >> 2) & 1;

    for (int p = 0; p <= T_STEPS; p++) {
        const int s1r = p & 1;          // h1(p-1) slot
        const int s1w = s1r ^ 1;        // h1(p) slot
        const int s2r = s1w;            // h2(p-2) slot
        const int s2w = s1r;            // h2(p-1) slot
        const bool doL1 = (p < T_STEPS);
        const bool doL2 = (p > 0);

        // ---- layer1(t=p): K split 8x64, partials to xchA ----
        float xw[4];
        if (doL1 && ks < 4) {
#pragma unroll
            for (int g = 0; g < 4; g++)
                xw[g] = g_XW1[(((size_t)p * 4 + g) * HID + col) * BATCH + b0 + ks];
        }
        if (doL1) {
            u64 acc[8];
#pragma unroll
            for (int i = 0; i < 8; i++) acc[i] = 0ULL;
            gemm_b4(g_h1buf + s1r * BH + (ks * 64) * BATCH + b0,
                    sm->w1 + (ks * 64) * 16 + oo * 4, 64, acc);
            u64* xc = sm->xchA + ks * 512 + r * 8;
#pragma unroll
            for (int i = 0; i < 8; i++) xc[i] = acc[i];
        }

        // ---- layer2(t=p-1): ks0-3 wi2 quarters (h1(p-1)), ks4-7 wh2 -------
        if (doL2) {
            u64 acc[8];
#pragma unroll
            for (int i = 0; i < 8; i++) acc[i] = 0ULL;
            if (ks < 4) {
                gemm_b4(g_h1buf + s1r * BH + (ks * 128) * BATCH + b0,
                        sm->wi2 + (ks * 128) * 16 + oo * 4, 128, acc);
            } else {
                gemm_b4(g_h2buf + s2r * BH + ((ks - 4) * 128) * BATCH + b0,
                        sm->wh2 + ((ks - 4) * 128) * 16 + oo * 4, 128, acc);
            }
            u64* xc = sm->xchB + ks * 512 + r * 8;
#pragma unroll
            for (int i = 0; i < 8; i++) xc[i] = acc[i];
        }

        __syncthreads();

        // ---- reduce + pointwise: ks0-3 -> layer1 (bb=ks), ks4-7 -> layer2 --
        if (doL1 && ks < 4) {
            const int bb = ks;
            const int ibase = bb * 2;
            u64 a0 = 0ULL, a1 = 0ULL;
#pragma unroll
            for (int s = 0; s < 8; s++) {
                const u64* xc = sm->xchA + s * 512 + r * 8 + ibase;
                add2(a0, xc[0]); add2(a1, xc[1]);
            }
            float2 iff = unpack2(a0);
            float2 go  = unpack2(a1);
            float iv = iff.x + xw[0];
            float fv = iff.y + xw[1];
            float gv = go.x  + xw[2];
            float ov = go.y  + xw[3];
            float c = sm->c1s[(b0 + bb) * 4 + oo];
            float cn = sigm(fv) * c + sigm(iv) * tanhf(gv);
            sm->c1s[(b0 + bb) * 4 + oo] = cn;
            g_h1buf[s1w * BH + col * BATCH + b0 + bb] = sigm(ov) * tanhf(cn);
        }
        if (doL2 && ks >= 4) {
            const int bb = ks - 4;
            const int ibase = bb * 2;
            u64 a0 = 0ULL, a1 = 0ULL;
#pragma unroll
            for (int s = 0; s < 8; s++) {
                const u64* xc = sm->xchB + s * 512 + r * 8 + ibase;
                add2(a0, xc[0]); add2(a1, xc[1]);
            }
            float2 iff = unpack2(a0);
            float2 go  = unpack2(a1);
            float c = sm->c2s[(b0 + bb) * 4 + oo];
            float cn = sigm(iff.y) * c + sigm(iff.x) * tanhf(go.x);
            sm->c2s[(b0 + bb) * 4 + oo] = cn;
            float hn = sigm(go.y) * tanhf(cn);
            g_h2buf[s2w * BH + col * BATCH + b0 + bb] = hn;
            int m = (p - 1) * BATCH + b0 + bb;
            g_AfragH2[afrag_idx(m, f_kc, f_ka, f_lk, f_khi)] = cvt_tf32(hn);
        }

        grid_barrier(p);
    }

    // final c slices (b-major, small)
    if (tid < 256) {
        int b = tid >> 2, oo2 = tid & 3;
        g_c1f[b * HID + o0 + oo2] = sm->c1s[tid];
        g_c2f[b * HID + o0 + oo2] = sm->c2s[tid];
    }
}

// ------------------------- decoder: tf32 mma, fragment-order + cp.async ------
#define DEC_SM_FLOATS (2 * 4096 + 2 * 8192)

__global__ __launch_bounds__(256, 1) void decoder_frag(
    const float* __restrict__ Afrag,
    const float* __restrict__ Bfrag,
    const float* __restrict__ bias,
    float* __restrict__ out)
{
    extern __shared__ float smf[];
    float* As = smf;            // [2][4096]
    float* Bs = smf + 8192;     // [2][8192]

    const int tid  = threadIdx.x;
    const int mb   = blockIdx.y;
    const int nb   = blockIdx.x;
    const int warp = tid >> 5, lane = tid & 31;
    const int wm = warp >> 2, wn = warp & 3;

    const float* Ag = Afrag + (size_t)mb * 16 * 4096;
    const float* Bg = Bfrag + (size_t)nb * 16 * 8192;

    float acc[4][8][4];
#pragma unroll
    for (int i = 0; i < 4; i++)
#pragma unroll
        for (int j = 0; j < 8; j++)
#pragma unroll
            for (int q = 0; q < 4; q++) acc[i][j][q] = 0.f;

#define DSTAGE(kc, buf)                                                        \
    {                                                                          \
        _Pragma("unroll")                                                      \
        for (int i = 0; i < 4; i++)                                            \
            cp_async16(As + (buf) * 4096 + (i * 256 + tid) * 4,                \
                       Ag + (kc) * 4096 + (i * 256 + tid) * 4);                \
        _Pragma("unroll")                                                      \
        for (int i = 0; i < 8; i++)                                            \
            cp_async16(Bs + (buf) * 8192 + (i * 256 + tid) * 4,                \
                       Bg + (kc) * 8192 + (i * 256 + tid) * 4);                \
    }

    DSTAGE(0, 0);
    cp_commit();

    for (int c = 0; c < 16; c++) {
        const int cur = c & 1, nxt = cur ^ 1;
        if (c < 15) { DSTAGE(c + 1, nxt); cp_commit(); cp_wait<1>(); }
        else        { cp_wait<0>(); }
        __syncthreads();
        const float* Ab = As + cur * 4096;
        const float* Bb = Bs + cur * 8192;
#pragma unroll
        for (int ka = 0; ka < 4; ka++) {
            uint4 af[4];
            uint2 bf[8];
#pragma unroll
            for (int i = 0; i < 4; i++)
                af[i] = *(const uint4*)(Ab + (((wm * 4 + i) * 4 + ka) * 32 + lane) * 4);
#pragma unroll
            for (int j = 0; j < 8; j++)
                bf[j] = *(const uint2*)(Bb + (((wn * 8 + j) * 4 + ka) * 32 + lane) * 2);
#pragma unroll
            for (int i = 0; i < 4; i++)
#pragma unroll
                for (int j = 0; j < 8; j++)
                    mma_tf32(acc[i][j], af[i], bf[j]);
        }
        __syncthreads();
    }
#undef DSTAGE

    const int g = lane >> 2, t4 = lane & 3;
#pragma unroll
    for (int i = 0; i < 4; i++) {
        int mrow = mb * 128 + wm * 64 + i * 16 + g;
#pragma unroll
        for (int j = 0; j < 8; j++) {
            int cb = nb * 256 + wn * 64 + j * 8 + t4 * 2;
            if (cb < VOCAB) {
                float bb0 = bias[cb], bb1 = bias[cb + 1];
                float2 v0 = make_float2(acc[i][j][0] + bb0, acc[i][j][1] + bb1);
                float2 v1 = make_float2(acc[i][j][2] + bb0, acc[i][j][3] + bb1);
                *(float2*)&out[(size_t)mrow * VOCAB + cb]       = v0;
                *(float2*)&out[(size_t)(mrow + 8) * VOCAB + cb] = v1;
            }
        }
    }
}

// ------------------------- finals (transpose back to b-major) ----------------
__global__ void write_finals(float* __restrict__ out) {
    int i = blockIdx.x * blockDim.x + threadIdx.x;
    if (i < BH) {
        int b = i / HID, k = i % HID;
        float* o = out + (size_t)T_STEPS * BATCH * VOCAB;
        // h1(99): written phase 99 -> slot 0; h2(99): written phase 100 -> slot 0
        o[i]          = g_h1buf[k * BATCH + b];
        o[BH + i]     = g_h2buf[k * BATCH + b];
        o[2 * BH + i] = g_c1f[i];
        o[3 * BH + i] = g_c2f[i];
    }
}

// ------------------------- launch -------------------------------------------
extern "C" void kernel_launch(void* const* d_in, const int* in_sizes, int n_in,
                              void* d_out, int out_size) {
    const int*   raw   = (const int*)  d_in[0];
    const float* h1    = (const float*)d_in[1];
    const float* h2    = (const float*)d_in[2];
    const float* c1    = (const float*)d_in[3];
    const float* c2    = (const float*)d_in[4];
    const float* emb   = (const float*)d_in[5];
    const float* wi1   = (const float*)d_in[6];
    const float* wh1   = (const float*)d_in[7];
    const float* wi2   = (const float*)d_in[8];
    const float* wh2   = (const float*)d_in[9];
    const float* dec_w = (const float*)d_in[10];
    const float* dec_b = (const float*)d_in[11];
    float* out = (float*)d_out;

    float *p_afrag, *p_bfrag;
    cudaGetSymbolAddress((void**)&p_afrag, g_AfragH2);
    cudaGetSymbolAddress((void**)&p_bfrag, g_BfragDec);

    static int attr_set = 0;
    if (!attr_set) {
        cudaFuncSetAttribute(lstm_recur, cudaFuncAttributeMaxDynamicSharedMemorySize,
                             (int)sizeof(SmemT));
        cudaFuncSetAttribute(decoder_frag, cudaFuncAttributeMaxDynamicSharedMemorySize,
                             DEC_SM_FLOATS * 4);
        attr_set = 1;
    }

    init_state<<<128, 256>>>(h1, h2);
    conv_b_dec<<<dim3(40, 64), 256>>>(dec_w);
    precompute_xw1<<<dim3(16, 50), 256>>>(raw, emb, wi1);
    lstm_recur<<<NBLK, 512, sizeof(SmemT)>>>(wh1, wi2, wh2, c1, c2);
    decoder_frag<<<dim3(40, 50), 256, DEC_SM_FLOATS * 4>>>(p_afrag, p_bfrag, dec_b, out);
    write_finals<<<128, 256>>>(out);
}

// round 15
// speedup vs baseline: 1.0878x; 1.0878x over previous
#include <cuda_runtime.h>
#include <cuda_bf16.h>
#include <math.h>

#define T_STEPS 100
#define BATCH   64
#define HID     512
#define NGATE   2048   // 4*512
#define VOCAB   10000
#define NVPAD   10240  // vocab padded to 256
#define NBLK    128
#define BH      (BATCH * HID)

typedef unsigned long long u64;

// ------------------------- scratch (static device memory) -------------------
__device__ float g_XW1[T_STEPS * 4 * HID * BATCH];    // [t][g][o][b] k-major
__device__ float g_AfragH2[T_STEPS * BATCH * HID];    // h2 in A-fragment order
__device__ float g_BfragDec[NVPAD * HID];             // dec_w in B-fragment order
__device__ float g_AfragEmb[T_STEPS * BATCH * HID];   // emb[tok] in A-frag order
__device__ float g_BfragWi1[NGATE * HID];             // wi1 in B-fragment order
__device__ float g_h1buf[2 * BH];                     // K-MAJOR: [k][64 b]
__device__ float g_h2buf[2 * BH];                     // K-MAJOR: [k][64 b]
__device__ float g_c1f[BH];
__device__ float g_c2f[BH];
__device__ unsigned g_bar_cnt;
__device__ volatile unsigned g_bar_flag;

// ------------------------- f32x2 helpers -------------------------------------
__device__ __forceinline__ u64 pack2(float x, float y) {
    u64 r;
    asm("mov.b64 %0, {%1, %2};" : "=l"(r)
        : "r"(__float_as_uint(x)), "r"(__float_as_uint(y)));
    return r;
}
__device__ __forceinline__ u64 dup2(float x) {
    u64 r;
    asm("mov.b64 %0, {%1, %1};" : "=l"(r) : "r"(__float_as_uint(x)));
    return r;
}
__device__ __forceinline__ void fma2(u64 &d, u64 a, u64 b) {
    asm("fma.rn.f32x2 %0, %1, %2, %0;" : "+l"(d) : "l"(a), "l"(b));
}
__device__ __forceinline__ void add2(u64 &d, u64 a) {
    asm("add.rn.f32x2 %0, %0, %1;" : "+l"(d) : "l"(a));
}
__device__ __forceinline__ float2 unpack2(u64 v) {
    float2 r;
    r.x = __uint_as_float((unsigned)(v & 0xFFFFFFFFu));
    r.y = __uint_as_float((unsigned)(v >> 32));
    return r;
}
__device__ __forceinline__ float sigm(float x) { return 1.f / (1.f + expf(-x)); }

// ------------------------- tf32 mma helpers ----------------------------------
__device__ __forceinline__ float cvt_tf32(float x) {
    unsigned r;
    asm("cvt.rn.tf32.f32 %0, %1;" : "=r"(r) : "f"(x));
    return __uint_as_float(r);
}
__device__ __forceinline__ void mma_tf32(float* d, const uint4& a, const uint2& b) {
    asm("mma.sync.aligned.m16n8k8.row.col.f32.tf32.tf32.f32 "
        "{%0,%1,%2,%3}, {%4,%5,%6,%7}, {%8,%9}, {%0,%1,%2,%3};"
        : "+f"(d[0]), "+f"(d[1]), "+f"(d[2]), "+f"(d[3])
        : "r"(a.x), "r"(a.y), "r"(a.z), "r"(a.w), "r"(b.x), "r"(b.y));
}

// ------------------------- cp.async helpers ----------------------------------
__device__ __forceinline__ void cp_async16(void* dst, const void* src) {
    unsigned d = (unsigned)__cvta_generic_to_shared(dst);
    asm volatile("cp.async.cg.shared.global [%0], [%1], 16;" :: "r"(d), "l"(src));
}
__device__ __forceinline__ void cp_commit() {
    asm volatile("cp.async.commit_group;");
}
template<int N> __device__ __forceinline__ void cp_wait() {
    asm volatile("cp.async.wait_group %0;" :: "n"(N));
}

// value (m, k) -> A-fragment global index (validated: recurrence->decoder path)
__device__ __forceinline__ size_t afrag_idx(int m, int kc, int ka, int lk, int khi) {
    int mb = m >> 7, mm = m & 127, matom = mm >> 4, r16 = mm & 15;
    int lane = (r16 & 7) * 4 + lk;
    int reg  = (r16 >> 3) + 2 * khi;
    return ((((size_t)(mb * 16 + kc) * 8 + matom) * 4 + ka) * 32 + lane) * 4 + reg;
}

// ------------------------- init (transpose states to k-major) ----------------
__global__ void init_state(const float* __restrict__ h1, const float* __restrict__ h2) {
    int i = blockIdx.x * blockDim.x + threadIdx.x;
    if (i < BH) {
        int k = i >> 6, b = i & 63;
        g_h1buf[i] = h1[b * HID + k];       // slot 0 = h1(-1)
        g_h2buf[BH + i] = h2[b * HID + k];
        g_h2buf[i] = h2[b * HID + k];       // slot 0 = h2(-1)
    }
    if (i == 0) { g_bar_cnt = 0; g_bar_flag = 0; }
}

// ------------------------- conv: dec_w -> B-fragment order -------------------
__global__ __launch_bounds__(256) void conv_b_dec(const float* __restrict__ Bw) {
    const int n  = blockIdx.x * 256 + threadIdx.x;   // 0..10239
    const int kg = blockIdx.y;                       // 0..63
    const int k0 = kg * 8;

    float v[8];
    if (n < VOCAB) {
        float4 a = *(const float4*)(Bw + (size_t)n * HID + k0);
        float4 b = *(const float4*)(Bw + (size_t)n * HID + k0 + 4);
        v[0]=a.x; v[1]=a.y; v[2]=a.z; v[3]=a.w;
        v[4]=b.x; v[5]=b.y; v[6]=b.z; v[7]=b.w;
    } else {
#pragma unroll
        for (int j = 0; j < 8; j++) v[j] = 0.f;
    }
    const int nb = n >> 8, nn = n & 255, natom = nn >> 3, g = nn & 7;
    const int kc = k0 >> 5, ka = (k0 & 31) >> 3;
    float* dst = g_BfragDec +
        ((((size_t)(nb * 16 + kc) * 32 + natom) * 4 + ka) * 32 + g * 4) * 2;
    float4 o0 = make_float4(cvt_tf32(v[0]), cvt_tf32(v[4]), cvt_tf32(v[1]), cvt_tf32(v[5]));
    float4 o1 = make_float4(cvt_tf32(v[2]), cvt_tf32(v[6]), cvt_tf32(v[3]), cvt_tf32(v[7]));
    *(float4*)dst       = o0;
    *(float4*)(dst + 4) = o1;
}

// ------------------------- conv: wi1 -> B-fragment order ---------------------
// n = g*512+o (0..2047); wi1 is [g][k][o] so per-k loads coalesce over o.
__global__ __launch_bounds__(256) void conv_b_wi1(const float* __restrict__ W) {
    const int n  = blockIdx.x * 256 + threadIdx.x;   // 0..2047
    const int kg = blockIdx.y;                       // 0..63
    const int k0 = kg * 8;
    const int gg = n >> 9, o = n & 511;

    float v[8];
#pragma unroll
    for (int j = 0; j < 8; j++)
        v[j] = W[((size_t)gg * HID + k0 + j) * HID + o];

    const int nb = n >> 8, nn = n & 255, natom = nn >> 3, g = nn & 7;
    const int kc = k0 >> 5, ka = (k0 & 31) >> 3;
    float* dst = g_BfragWi1 +
        ((((size_t)(nb * 16 + kc) * 32 + natom) * 4 + ka) * 32 + g * 4) * 2;
    float4 o0 = make_float4(cvt_tf32(v[0]), cvt_tf32(v[4]), cvt_tf32(v[1]), cvt_tf32(v[5]));
    float4 o1 = make_float4(cvt_tf32(v[2]), cvt_tf32(v[6]), cvt_tf32(v[3]), cvt_tf32(v[7]));
    *(float4*)dst       = o0;
    *(float4*)(dst + 4) = o1;
}

// ------------------------- conv: emb[tok] -> A-fragment order ----------------
// block: 32 m-rows x 8 octets (64 k).  grid (200, 8).
__global__ __launch_bounds__(256) void conv_a_emb(
    const int* __restrict__ tok, const float* __restrict__ emb)
{
    const int tid = threadIdx.x;
    const int m  = blockIdx.x * 32 + (tid >> 3);
    const int k0 = blockIdx.y * 64 + (tid & 7) * 8;
    const int t  = tok[m];

    float4 a = *(const float4*)(emb + (size_t)t * HID + k0);
    float4 b = *(const float4*)(emb + (size_t)t * HID + k0 + 4);
    float v[8] = {a.x, a.y, a.z, a.w, b.x, b.y, b.z, b.w};

    const int kc = k0 >> 5, ka = (k0 & 31) >> 3;
#pragma unroll
    for (int j = 0; j < 8; j++) {
        int lk = j & 3, khi = j >> 2;
        g_AfragEmb[afrag_idx(m, kc, ka, lk, khi)] = cvt_tf32(v[j]);
    }
}

// ------------------------- tf32 mma GEMM core (shared by both) ---------------
#define DEC_SM_FLOATS (2 * 4096 + 2 * 8192)

#define MMA_MAIN(ACCDECL)                                                      \
    extern __shared__ float smf[];                                             \
    float* As = smf;                                                           \
    float* Bs = smf + 8192;                                                    \
    const int tid  = threadIdx.x;                                              \
    const int mb   = blockIdx.y;                                               \
    const int nb   = blockIdx.x;                                               \
    const int warp = tid >> 5, lane = tid & 31;                                \
    const int wm = warp >> 2, wn = warp & 3;                                   \
    const float* Ag = Afrag + (size_t)mb * 16 * 4096;                          \
    const float* Bg = Bfrag + (size_t)nb * 16 * 8192;                          \
    ACCDECL                                                                    \
    {                                                                          \
        _Pragma("unroll")                                                      \
        for (int i = 0; i < 4; i++)                                            \
            cp_async16(As + (i * 256 + tid) * 4, Ag + (i * 256 + tid) * 4);    \
        _Pragma("unroll")                                                      \
        for (int i = 0; i < 8; i++)                                            \
            cp_async16(Bs + (i * 256 + tid) * 4, Bg + (i * 256 + tid) * 4);    \
        cp_commit();                                                           \
    }                                                                          \
    for (int c = 0; c < 16; c++) {                                             \
        const int cur = c & 1, nxt = cur ^ 1;                                  \
        if (c < 15) {                                                          \
            _Pragma("unroll")                                                  \
            for (int i = 0; i < 4; i++)                                        \
                cp_async16(As + nxt * 4096 + (i * 256 + tid) * 4,              \
                           Ag + (c + 1) * 4096 + (i * 256 + tid) * 4);         \
            _Pragma("unroll")                                                  \
            for (int i = 0; i < 8; i++)                                        \
                cp_async16(Bs + nxt * 8192 + (i * 256 + tid) * 4,              \
                           Bg + (c + 1) * 8192 + (i * 256 + tid) * 4);         \
            cp_commit(); cp_wait<1>();                                         \
        } else { cp_wait<0>(); }                                               \
        __syncthreads();                                                       \
        const float* Ab = As + cur * 4096;                                     \
        const float* Bb = Bs + cur * 8192;                                     \
        _Pragma("unroll")                                                      \
        for (int ka = 0; ka < 4; ka++) {                                       \
            uint4 af[4];                                                       \
            uint2 bf[8];                                                       \
            _Pragma("unroll")                                                  \
            for (int i = 0; i < 4; i++)                                        \
                af[i] = *(const uint4*)(Ab + (((wm*4+i)*4+ka)*32 + lane) * 4); \
            _Pragma("unroll")                                                  \
            for (int j = 0; j < 8; j++)                                        \
                bf[j] = *(const uint2*)(Bb + (((wn*8+j)*4+ka)*32 + lane) * 2); \
            _Pragma("unroll")                                                  \
            for (int i = 0; i < 4; i++)                                        \
                _Pragma("unroll")                                              \
                for (int j = 0; j < 8; j++)                                    \
                    mma_tf32(acc[i][j], af[i], bf[j]);                         \
        }                                                                      \
        __syncthreads();                                                       \
    }

#define ACC_DECL                                                               \
    float acc[4][8][4];                                                        \
    _Pragma("unroll")                                                          \
    for (int i = 0; i < 4; i++)                                                \
        _Pragma("unroll")                                                      \
        for (int j = 0; j < 8; j++)                                            \
            _Pragma("unroll")                                                  \
            for (int q = 0; q < 4; q++) acc[i][j][q] = 0.f;

// ------------------------- precompute XW1 via tf32 mma -----------------------
// grid (8 nb, 50 mb).  Epilogue scatters into g_XW1[t][g][o][b].
__global__ __launch_bounds__(256, 1) void precompute_mma(
    const float* __restrict__ Afrag,
    const float* __restrict__ Bfrag)
{
    MMA_MAIN(ACC_DECL)

    const int g_ = lane >> 2, t4 = lane & 3;
#pragma unroll
    for (int i = 0; i < 4; i++) {
        int m0r = mb * 128 + wm * 64 + i * 16 + g_;
#pragma unroll
        for (int j = 0; j < 8; j++) {
            int nc = nb * 256 + wn * 64 + j * 8 + t4 * 2;
            int gg = nc >> 9, o = nc & 511;
#pragma unroll
            for (int q = 0; q < 4; q++) {
                int m = m0r + (q >> 1) * 8;
                int oo = o + (q & 1);
                int t = m >> 6, b = m & 63;
                g_XW1[(((size_t)t * 4 + gg) * HID + oo) * BATCH + b] = acc[i][j][q];
            }
        }
    }
}

// ------------------------- decoder: tf32 mma + bias + guard ------------------
__global__ __launch_bounds__(256, 1) void decoder_frag(
    const float* __restrict__ Afrag,
    const float* __restrict__ Bfrag,
    const float* __restrict__ bias,
    float* __restrict__ out)
{
    MMA_MAIN(ACC_DECL)

    const int g = lane >> 2, t4 = lane & 3;
#pragma unroll
    for (int i = 0; i < 4; i++) {
        int mrow = mb * 128 + wm * 64 + i * 16 + g;
#pragma unroll
        for (int j = 0; j < 8; j++) {
            int cb = nb * 256 + wn * 64 + j * 8 + t4 * 2;
            if (cb < VOCAB) {
                float bb0 = bias[cb], bb1 = bias[cb + 1];
                float2 v0 = make_float2(acc[i][j][0] + bb0, acc[i][j][1] + bb1);
                float2 v1 = make_float2(acc[i][j][2] + bb0, acc[i][j][3] + bb1);
                *(float2*)&out[(size_t)mrow * VOCAB + cb]       = v0;
                *(float2*)&out[(size_t)(mrow + 8) * VOCAB + cb] = v1;
            }
        }
    }
}

// ------------------------- persistent recurrence kernel (R13) ----------------
struct SmemT {
    float w1 [HID * 16];    // [k][oo][g]
    float wi2[HID * 16];
    float wh2[HID * 16];
    u64   xchA[8 * 64 * 8]; // layer1 partials [ks][r][8]
    u64   xchB[8 * 64 * 8]; // layer2 partials [ks][r][8]
    float c1s[256];         // [b][oo]
    float c2s[256];
};

__device__ __forceinline__ void grid_barrier(int p) {
    __syncthreads();
    if (threadIdx.x == 0) {
        __threadfence();   // release (emits CCTL.IVALL too)
        unsigned prev = atomicAdd(&g_bar_cnt, 1u);
        if (prev == (unsigned)NBLK * (unsigned)(p + 1) - 1u) {
            g_bar_flag = (unsigned)(p + 1);
        } else {
            while (g_bar_flag < (unsigned)(p + 1)) { }
        }
        __threadfence();   // acquire + invalidate this SM's L1D
    }
    __syncthreads();
}

// acc[b*2+0] = {i,f}, acc[b*2+1] = {g,o} for 4 batches b.
__device__ __forceinline__ void gemm_b4(
    const float* __restrict__ hk,     // k-major h + b0 offset
    const float* __restrict__ w,      // smem weights + oo*4
    int klen, u64 (&acc)[8])
{
#pragma unroll 2
    for (int kk = 0; kk < klen; kk += 4) {
        float4 hv[4];
#pragma unroll
        for (int j = 0; j < 4; j++)
            hv[j] = *(const float4*)(hk + (size_t)(kk + j) * BATCH);
#pragma unroll
        for (int j = 0; j < 4; j++) {
            float4 wv = *(const float4*)(w + (kk + j) * 16);
            u64 w0 = ((const u64*)&wv)[0];
            u64 w1 = ((const u64*)&wv)[1];
            u64 d0 = dup2(hv[j].x), d1 = dup2(hv[j].y);
            u64 d2 = dup2(hv[j].z), d3 = dup2(hv[j].w);
            fma2(acc[0], d0, w0); fma2(acc[1], d0, w1);
            fma2(acc[2], d1, w0); fma2(acc[3], d1, w1);
            fma2(acc[4], d2, w0); fma2(acc[5], d2, w1);
            fma2(acc[6], d3, w0); fma2(acc[7], d3, w1);
        }
    }
}

__global__ __launch_bounds__(512, 1) void lstm_recur(
    const float* __restrict__ wh1, const float* __restrict__ wi2g,
    const float* __restrict__ wh2g,
    const float* __restrict__ c1in, const float* __restrict__ c2in)
{
    extern __shared__ char smraw[];
    SmemT* sm = (SmemT*)smraw;
    const int tid = threadIdx.x;
    const int bi  = blockIdx.x;
    const int o0  = bi * 4;

    for (int idx = tid; idx < HID * 16; idx += 512) {
        int k = idx >> 4, c = idx & 15;
        int oo = c >> 2, g = c & 3;
        size_t src = ((size_t)g * HID + k) * HID + o0 + oo;
        sm->w1 [idx] = wh1 [src];
        sm->wi2[idx] = wi2g[src];
        sm->wh2[idx] = wh2g[src];
    }
    if (tid < 256) {
        int b = tid >> 2, oo = tid & 3;
        sm->c1s[tid] = c1in[b * HID + o0 + oo];
        sm->c2s[tid] = c2in[b * HID + o0 + oo];
    }
    __syncthreads();

    const int ks = tid >> 6;        // 0..7
    const int r  = tid & 63;
    const int oo = r & 3;
    const int bq = r >> 2;
    const int b0 = bq * 4;
    const int col = o0 + oo;

    const int f_kc = col >> 5, f_kk = col & 31;
    const int f_ka = f_kk >> 3, f_lk = f_kk & 3, f_khi = (f_kk >> 2) & 1;

    for (int p = 0; p <= T_STEPS; p++) {
        const int s1r = p & 1;
        const int s1w = s1r ^ 1;
        const int s2r = s1w;
        const int s2w = s1r;
        const bool doL1 = (p < T_STEPS);
        const bool doL2 = (p > 0);

        float xw[4];
        if (doL1 && ks < 4) {
#pragma unroll
            for (int g = 0; g < 4; g++)
                xw[g] = g_XW1[(((size_t)p * 4 + g) * HID + col) * BATCH + b0 + ks];
        }
        if (doL1) {
            u64 acc[8];
#pragma unroll
            for (int i = 0; i < 8; i++) acc[i] = 0ULL;
            gemm_b4(g_h1buf + s1r * BH + (ks * 64) * BATCH + b0,
                    sm->w1 + (ks * 64) * 16 + oo * 4, 64, acc);
            u64* xc = sm->xchA + ks * 512 + r * 8;
#pragma unroll
            for (int i = 0; i < 8; i++) xc[i] = acc[i];
        }

        if (doL2) {
            u64 acc[8];
#pragma unroll
            for (int i = 0; i < 8; i++) acc[i] = 0ULL;
            if (ks < 4) {
                gemm_b4(g_h1buf + s1r * BH + (ks * 128) * BATCH + b0,
                        sm->wi2 + (ks * 128) * 16 + oo * 4, 128, acc);
            } else {
                gemm_b4(g_h2buf + s2r * BH + ((ks - 4) * 128) * BATCH + b0,
                        sm->wh2 + ((ks - 4) * 128) * 16 + oo * 4, 128, acc);
            }
            u64* xc = sm->xchB + ks * 512 + r * 8;
#pragma unroll
            for (int i = 0; i < 8; i++) xc[i] = acc[i];
        }

        __syncthreads();

        if (doL1 && ks < 4) {
            const int bb = ks;
            const int ibase = bb * 2;
            u64 a0 = 0ULL, a1 = 0ULL;
#pragma unroll
            for (int s = 0; s < 8; s++) {
                const u64* xc = sm->xchA + s * 512 + r * 8 + ibase;
                add2(a0, xc[0]); add2(a1, xc[1]);
            }
            float2 iff = unpack2(a0);
            float2 go  = unpack2(a1);
            float iv = iff.x + xw[0];
            float fv = iff.y + xw[1];
            float gv = go.x  + xw[2];
            float ov = go.y  + xw[3];
            float c = sm->c1s[(b0 + bb) * 4 + oo];
            float cn = sigm(fv) * c + sigm(iv) * tanhf(gv);
            sm->c1s[(b0 + bb) * 4 + oo] = cn;
            g_h1buf[s1w * BH + col * BATCH + b0 + bb] = sigm(ov) * tanhf(cn);
        }
        if (doL2 && ks >= 4) {
            const int bb = ks - 4;
            const int ibase = bb * 2;
            u64 a0 = 0ULL, a1 = 0ULL;
#pragma unroll
            for (int s = 0; s < 8; s++) {
                const u64* xc = sm->xchB + s * 512 + r * 8 + ibase;
                add2(a0, xc[0]); add2(a1, xc[1]);
            }
            float2 iff = unpack2(a0);
            float2 go  = unpack2(a1);
            float c = sm->c2s[(b0 + bb) * 4 + oo];
            float cn = sigm(iff.y) * c + sigm(iff.x) * tanhf(go.x);
            sm->c2s[(b0 + bb) * 4 + oo] = cn;
            float hn = sigm(go.y) * tanhf(cn);
            g_h2buf[s2w * BH + col * BATCH + b0 + bb] = hn;
            int m = (p - 1) * BATCH + b0 + bb;
            g_AfragH2[afrag_idx(m, f_kc, f_ka, f_lk, f_khi)] = cvt_tf32(hn);
        }

        grid_barrier(p);
    }

    if (tid < 256) {
        int b = tid >> 2, oo2 = tid & 3;
        g_c1f[b * HID + o0 + oo2] = sm->c1s[tid];
        g_c2f[b * HID + o0 + oo2] = sm->c2s[tid];
    }
}

// ------------------------- finals (transpose back to b-major) ----------------
__global__ void write_finals(float* __restrict__ out) {
    int i = blockIdx.x * blockDim.x + threadIdx.x;
    if (i < BH) {
        int b = i / HID, k = i % HID;
        float* o = out + (size_t)T_STEPS * BATCH * VOCAB;
        o[i]          = g_h1buf[k * BATCH + b];
        o[BH + i]     = g_h2buf[k * BATCH + b];
        o[2 * BH + i] = g_c1f[i];
        o[3 * BH + i] = g_c2f[i];
    }
}

// ------------------------- launch -------------------------------------------
extern "C" void kernel_launch(void* const* d_in, const int* in_sizes, int n_in,
                              void* d_out, int out_size) {
    const int*   raw   = (const int*)  d_in[0];
    const float* h1    = (const float*)d_in[1];
    const float* h2    = (const float*)d_in[2];
    const float* c1    = (const float*)d_in[3];
    const float* c2    = (const float*)d_in[4];
    const float* emb   = (const float*)d_in[5];
    const float* wi1   = (const float*)d_in[6];
    const float* wh1   = (const float*)d_in[7];
    const float* wi2   = (const float*)d_in[8];
    const float* wh2   = (const float*)d_in[9];
    const float* dec_w = (const float*)d_in[10];
    const float* dec_b = (const float*)d_in[11];
    float* out = (float*)d_out;

    float *p_afragH2, *p_bfragDec, *p_afragEmb, *p_bfragWi1;
    cudaGetSymbolAddress((void**)&p_afragH2,  g_AfragH2);
    cudaGetSymbolAddress((void**)&p_bfragDec, g_BfragDec);
    cudaGetSymbolAddress((void**)&p_afragEmb, g_AfragEmb);
    cudaGetSymbolAddress((void**)&p_bfragWi1, g_BfragWi1);

    static int attr_set = 0;
    if (!attr_set) {
        cudaFuncSetAttribute(lstm_recur, cudaFuncAttributeMaxDynamicSharedMemorySize,
                             (int)sizeof(SmemT));
        cudaFuncSetAttribute(decoder_frag, cudaFuncAttributeMaxDynamicSharedMemorySize,
                             DEC_SM_FLOATS * 4);
        cudaFuncSetAttribute(precompute_mma, cudaFuncAttributeMaxDynamicSharedMemorySize,
                             DEC_SM_FLOATS * 4);
        attr_set = 1;
    }

    init_state<<<128, 256>>>(h1, h2);
    conv_b_dec<<<dim3(40, 64), 256>>>(dec_w);
    conv_a_emb<<<dim3(200, 8), 256>>>(raw, emb);
    conv_b_wi1<<<dim3(8, 64), 256>>>(wi1);
    precompute_mma<<<dim3(8, 50), 256, DEC_SM_FLOATS * 4>>>(p_afragEmb, p_bfragWi1);
    lstm_recur<<<NBLK, 512, sizeof(SmemT)>>>(wh1, wi2, wh2, c1, c2);
    decoder_frag<<<dim3(40, 50), 256, DEC_SM_FLOATS * 4>>>(p_afragH2, p_bfragDec, dec_b, out);
    write_finals<<<128, 256>>>(out);
}